// round 14
// baseline (speedup 1.0000x reference)
#include <cuda_runtime.h>
#include <cuda_bf16.h>
#include <cstdint>

#define NB      1024
#define NNODES  10000
#define NROOTS  4
#define MNODES  (NNODES - NROOTS)   // 9996
#define NCONF   16
#define NRG     32
#define NPAD    10016
#define NQ      (MNODES / 4)        // 2499 node-quads

// Transposed bit-pack, rg-major: g_evt[rg*NPAD + n] bit r = ev[rg*32+r][n]
__device__ uint32_t g_evt[NRG * NPAD];       // 1.28 MB
// Conf-major pre-sigmoided CPT: g_sigT4[c*NQ + q] = (sig[4q][c],..,sig[4q+3][c])
__device__ float4   g_sigT4[NCONF * NQ];     // 640 KB

// ---------------------------------------------------------------------------
// Kernel A (fused): blocks [0,628) bit-transpose pack; [628,638) sigmoid +
// conf-major transpose (one-time, strided reads are fine here).
// ---------------------------------------------------------------------------
#define PACK_TILES   157                    // ceil(10000/64)
#define PACK_BLOCKS  (PACK_TILES * 32 / 8)  // 628
#define SIGT_BLOCKS  ((NQ + 255) / 256)     // 10

__global__ __launch_bounds__(256)
void pack_sig_kernel(const int* __restrict__ ev, const float4* __restrict__ cpt4) {
    if (blockIdx.x >= PACK_BLOCKS) {
        int q = (blockIdx.x - PACK_BLOCKS) * 256 + threadIdx.x;
        if (q < NQ) {
            float s[4][16];
            #pragma unroll
            for (int j = 0; j < 4; j++) {
                const float4* row = cpt4 + (size_t)(4 * q + j) * 4;
                #pragma unroll
                for (int w = 0; w < 4; w++) {
                    float4 x = row[w];
                    s[j][4*w+0] = 1.0f / (1.0f + __expf(-x.x));
                    s[j][4*w+1] = 1.0f / (1.0f + __expf(-x.y));
                    s[j][4*w+2] = 1.0f / (1.0f + __expf(-x.z));
                    s[j][4*w+3] = 1.0f / (1.0f + __expf(-x.w));
                }
            }
            #pragma unroll
            for (int c = 0; c < 16; c++)
                g_sigT4[c * NQ + q] = make_float4(s[0][c], s[1][c], s[2][c], s[3][c]);
        }
        return;
    }

    const int g    = blockIdx.x * 8 + (threadIdx.x >> 5);
    const int lane = threadIdx.x & 31;
    const int rg   = g & 31;
    const int tile = g >> 5;                 // 0..156
    const int n    = tile * 64 + lane * 2;
    if (n >= NNODES) return;                 // NNODES even: pairs never straddle

    const int* __restrict__ base = ev + (size_t)(rg * 32) * NNODES + n;
    uint32_t a0 = 0, a1 = 0;
    #pragma unroll 8
    for (int r = 0; r < 32; r++) {
        int2 v = *(const int2*)(base + (size_t)r * NNODES);
        a0 |= (uint32_t)(v.x & 1) << r;
        a1 |= (uint32_t)(v.y & 1) << r;
    }
    *(uint2*)(g_evt + rg * NPAD + n) = make_uint2(a0, a1);
}

// ---------------------------------------------------------------------------
// Kernel B: main. T=128, thread owns node-quad q (nodes 4q..4q+3) for one
// 32-row group. Staging: 16 coalesced LDG.128 from g_sigT4 + 64 conflict-free
// STS. Hot loop: 4 confs + 4 conflict-free LDS + 1 STG.128 per row.
// ---------------------------------------------------------------------------
#define THREADS 128

__global__ __launch_bounds__(THREADS)
void bayes_main(const int4*  __restrict__ parents4,
                const float* __restrict__ root_logits,
                float*       __restrict__ out) {
    __shared__ float slot[NCONF * 4 * THREADS];        // 32 KB

    const int rg  = blockIdx.y;
    const int b0  = rg * 32;
    const int tid = threadIdx.x;
    const int q   = blockIdx.x * THREADS + tid;

    if (blockIdx.x == 0) {                             // 32 rows x 4 roots
        int r = tid & (NROOTS - 1), row = tid >> 2;
        float x = root_logits[r];
        out[(size_t)(b0 + row) * NNODES + r] = 1.0f / (1.0f + __expf(-x));
    }
    if (q >= NQ) return;
    const int i0 = 4 * q;

    // Parent bit-words: 4 nodes x 4 parents
    const uint32_t* __restrict__ evt = g_evt + rg * NPAD;
    uint32_t w[4][4];
    #pragma unroll
    for (int j = 0; j < 4; j++) {
        const int4 p = parents4[i0 + j];
        w[j][0] = evt[p.x];   // bit3
        w[j][1] = evt[p.y];   // bit2
        w[j][2] = evt[p.z];   // bit1
        w[j][3] = evt[p.w];   // bit0
    }

    // Coalesced staging: one LDG.128 per conf delivers all 4 nodes' values
    #pragma unroll
    for (int c = 0; c < NCONF; c++) {
        float4 v = g_sigT4[c * NQ + q];
        slot[(c * 4 + 0) * THREADS + tid] = v.x;
        slot[(c * 4 + 1) * THREADS + tid] = v.y;
        slot[(c * 4 + 2) * THREADS + tid] = v.z;
        slot[(c * 4 + 3) * THREADS + tid] = v.w;
    }

    float* obase = out + (size_t)b0 * NNODES + NROOTS + i0;  // 16B aligned
    #pragma unroll
    for (int r = 0; r < 32; r++) {
        float v[4];
        #pragma unroll
        for (int j = 0; j < 4; j++) {
            unsigned c = (((w[j][0] >> r) & 1u) << 3)
                       | (((w[j][1] >> r) & 1u) << 2)
                       | (((w[j][2] >> r) & 1u) << 1)
                       |  ((w[j][3] >> r) & 1u);
            v[j] = slot[(c * 4 + j) * THREADS + tid];  // bank = tid%32
        }
        *(float4*)(obase + (size_t)r * NNODES) = make_float4(v[0], v[1], v[2], v[3]);
    }
}

// ---------------------------------------------------------------------------
extern "C" void kernel_launch(void* const* d_in, const int* in_sizes, int n_in,
                              void* d_out, int out_size) {
    const int*    ev      = (const int*)d_in[0];
    const int4*   parents = (const int4*)d_in[1];
    const float*  roots   = (const float*)d_in[2];
    const float4* cpt4    = (const float4*)d_in[3];
    float*        out     = (float*)d_out;

    pack_sig_kernel<<<PACK_BLOCKS + SIGT_BLOCKS, 256>>>(ev, cpt4);

    dim3 gmain((NQ + THREADS - 1) / THREADS, NRG);     // (20, 32)
    bayes_main<<<gmain, THREADS>>>(parents, roots, out);
}